// round 6
// baseline (speedup 1.0000x reference)
#include <cuda_runtime.h>
#include <math.h>

// Scratch for per-query MLP weights (N x cols). 4096*80 floats = 1.25 MB.
__device__ float g_weights[4096 * 80];

// ===========================================================================
// GEMM (fast path, dim=256, cols=65): weights = q @ Wg + bg.
// 150 CTAs x 256 threads, 16 n per CTA. K-SPLIT: warp w owns d in
// [32w, 32w+32); each lane accumulates ALL 16 n for its column pair
// (2l, 2l+1) in registers -> Wg rows cross the smem crossbar ONCE per warp.
// q stored transposed (stride 20 for alignment+banking) so the 16 q values
// per d come from 4 LDS.128 broadcasts. Lane 0 carries column 64.
// Tree-reduce partials across the 8 warps through smem.
// ===========================================================================
#define GSW   0                    // swg: 256 x 66 (padded) = 16896 floats
#define GSQ   16896                // sqT: 256 x 20            = 5120 floats
#define GPR   22016                // partials: 8*16 x 66      = 8448 floats
#define GP64  30464                // col64 partials: 8*16     = 128 floats
#define GTOT  30592

__global__ void __launch_bounds__(256)
posmlp_gemm_ksplit_kernel(const float* __restrict__ q,
                          const float* __restrict__ Wg,
                          const float* __restrict__ bg,
                          float* __restrict__ w_out) {
    extern __shared__ float sm[];
    const int n0   = blockIdx.x * 16;
    const int tid  = threadIdx.x;
    const int w    = tid >> 5;
    const int l    = tid & 31;

    // Stage Wg into padded (stride 66) smem; coalesced LDG.
    #pragma unroll 5
    for (int i = tid; i < 256 * 65; i += 256) {
        const int d = i / 65;
        const int c = i - d * 65;
        sm[GSW + d * 66 + c] = Wg[i];
    }
    // Stage q transposed: sqT[d*20 + nn] = q[(n0+nn)*256 + d].
    #pragma unroll
    for (int i = tid; i < 4096; i += 256) {
        const int nn = i >> 8;
        const int d  = i & 255;
        sm[GSQ + d * 20 + nn] = q[(size_t)n0 * 256 + i];
    }
    __syncthreads();

    const int d0 = w * 32;
    float2 acc[16];
    #pragma unroll
    for (int nn = 0; nn < 16; nn++) acc[nn] = make_float2(0.f, 0.f);
    float acc64[16];
    #pragma unroll
    for (int nn = 0; nn < 16; nn++) acc64[nn] = 0.f;

    #pragma unroll 4
    for (int dd = 0; dd < 32; dd++) {
        const int d = d0 + dd;
        const float2 wp = *reinterpret_cast<const float2*>(&sm[GSW + d * 66 + 2 * l]);
        const float w64 = sm[GSW + d * 66 + 64];
        const float4 qa = *reinterpret_cast<const float4*>(&sm[GSQ + d * 20 + 0]);
        const float4 qb = *reinterpret_cast<const float4*>(&sm[GSQ + d * 20 + 4]);
        const float4 qc = *reinterpret_cast<const float4*>(&sm[GSQ + d * 20 + 8]);
        const float4 qd = *reinterpret_cast<const float4*>(&sm[GSQ + d * 20 + 12]);
        const float qv[16] = {qa.x, qa.y, qa.z, qa.w, qb.x, qb.y, qb.z, qb.w,
                              qc.x, qc.y, qc.z, qc.w, qd.x, qd.y, qd.z, qd.w};
        #pragma unroll
        for (int nn = 0; nn < 16; nn++) {
            acc[nn].x = fmaf(qv[nn], wp.x, acc[nn].x);
            acc[nn].y = fmaf(qv[nn], wp.y, acc[nn].y);
        }
        if (l == 0) {
            #pragma unroll
            for (int nn = 0; nn < 16; nn++)
                acc64[nn] = fmaf(qv[nn], w64, acc64[nn]);
        }
    }

    // Write partials.
    #pragma unroll
    for (int nn = 0; nn < 16; nn++) {
        *reinterpret_cast<float2*>(&sm[GPR + (w * 16 + nn) * 66 + 2 * l]) = acc[nn];
    }
    if (l == 0) {
        #pragma unroll
        for (int nn = 0; nn < 16; nn++) sm[GP64 + w * 16 + nn] = acc64[nn];
    }
    __syncthreads();

    // Reduce 8 partials per output; 16n x 65c = 1040 outputs.
    for (int o = tid; o < 1040; o += 256) {
        const int nn = o / 65;
        const int c  = o - nn * 65;
        float s = 0.f;
        if (c < 64) {
            #pragma unroll
            for (int w8 = 0; w8 < 8; w8++) s += sm[GPR + (w8 * 16 + nn) * 66 + c];
        } else {
            #pragma unroll
            for (int w8 = 0; w8 < 8; w8++) s += sm[GP64 + w8 * 16 + nn];
        }
        w_out[(size_t)(n0 + nn) * 65 + c] = s + bg[c];
    }
}

// ===========================================================================
// Main kernel (H=W=64, hidden=16): breakpoint/prefix sweep.
// One CTA per n, 128 threads: thread t owns row y=t>>1, half-row x local
// in [0,32) at global offset (t&1)*32.
// For unit k: pre(xl) = s*xl + c (linear). relu switches once at t=-c/s.
// Scatter (alpha=w2*s, beta=w2*c) into a per-thread difference array
// bins[0..32] (interleaved [b][tid] layout: conflict-free), then prefix
// sweep: A+=dA, B+=dB, out = A*xl + B. ~4 ops/pixel instead of 32 FLOPs.
// Exact: boundary pre==0 terms contribute exactly 0 either way.
// ===========================================================================
__global__ void __launch_bounds__(128)
posmlp_bp64_kernel(const float* __restrict__ pos,
                   const float* __restrict__ wts,
                   float* __restrict__ out) {
    __shared__ float  sw[65];
    __shared__ float2 bins[33 * 128];

    const int n   = blockIdx.x;
    const int tid = threadIdx.x;

    if (tid < 65) sw[tid] = wts[(size_t)n * 65 + tid];
    __syncthreads();

    const float cx = pos[(size_t)n * 4 + 0];
    const float cy = pos[(size_t)n * 4 + 1];
    const float bw = pos[(size_t)n * 4 + 2];
    const float bh = pos[(size_t)n * 4 + 3];
    const float inv_bw = 1.0f / bw;
    const float inv_bh = 1.0f / bh;

    const int y    = tid >> 1;
    const int half = tid & 1;

    const float rel_y = (((float)y + 0.5f) * (1.0f / 64.0f) - cy) * inv_bh;
    const float sx  = inv_bw * (1.0f / 64.0f);
    const float tx  = (0.5f * (1.0f / 64.0f) - cx) * inv_bw;
    const float txh = fmaf(32.0f * (float)half, sx, tx);   // local-x origin

    // Zero private bins (no sync needed: bins are per-thread private).
    #pragma unroll
    for (int b = 0; b < 33; b++) bins[b * 128 + tid] = make_float2(0.f, 0.f);

    float A0 = 0.f;
    float B0 = sw[64];   // b2 folded in

    #pragma unroll
    for (int k = 0; k < 16; k++) {
        const float w0 = sw[k];
        const float ay = fmaf(rel_y, sw[16 + k], sw[32 + k]);
        const float w2 = sw[48 + k];
        const float s  = w0 * sx;                 // slope in local x
        const float c  = fmaf(w0, txh, ay);       // intercept in local x
        const float alpha = w2 * s;
        const float beta  = w2 * c;
        if (s != 0.f) {
            const float t = __fdividef(-c, s);
            const int bidx = (int)fminf(fmaxf(ceilf(t), 0.f), 32.f);
            float2 v = bins[bidx * 128 + tid];
            if (s > 0.f) {              // active for xl >= bidx
                v.x += alpha; v.y += beta;
            } else {                    // active for xl < bidx
                A0 += alpha; B0 += beta;
                v.x -= alpha; v.y -= beta;
            }
            bins[bidx * 128 + tid] = v;
        } else if (c > 0.f) {           // constant-active unit (alpha == +-0)
            B0 += beta;
        }
    }

    // Prefix sweep over 32 local pixels; float4 coalesced stores.
    float A = A0, B = B0;
    float xf = 0.f;
    float* orow = out + (((size_t)n * 64 + y) * 64 + half * 32);

    #pragma unroll
    for (int xi = 0; xi < 32; xi += 4) {
        float4 res;
        float* rp = &res.x;
        #pragma unroll
        for (int j = 0; j < 4; j++) {
            const float2 d = bins[(xi + j) * 128 + tid];
            A += d.x;
            B += d.y;
            rp[j] = fmaf(A, xf, B);
            xf += 1.0f;
        }
        *reinterpret_cast<float4*>(orow + xi) = res;
    }
}

// ===========================================================================
// Fallback path (other shapes).
// ===========================================================================
__global__ void posmlp_gemm_kernel(const float* __restrict__ q,
                                   const float* __restrict__ Wg,
                                   const float* __restrict__ bg,
                                   float* __restrict__ w_out,
                                   int dim, int cols) {
    extern __shared__ float sqf[];
    const int n = blockIdx.x;
    const float* qr = q + (size_t)n * dim;
    for (int d = threadIdx.x; d < dim; d += blockDim.x) sqf[d] = qr[d];
    __syncthreads();
    for (int j = threadIdx.x; j < cols; j += blockDim.x) {
        float acc = bg[j];
        #pragma unroll 8
        for (int d = 0; d < dim; d++) {
            acc = fmaf(sqf[d], Wg[(size_t)d * cols + j], acc);
        }
        w_out[(size_t)n * cols + j] = acc;
    }
}

__global__ void posmlp_generic_kernel(const float* __restrict__ pos,
                                      const float* __restrict__ wts,
                                      float* __restrict__ out,
                                      int H, int W, int h, int cols) {
    const int n = blockIdx.x;
    const float* w = wts + (size_t)n * cols;
    const float cx = pos[(size_t)n * 4 + 0];
    const float cy = pos[(size_t)n * 4 + 1];
    const float bw = pos[(size_t)n * 4 + 2];
    const float bh = pos[(size_t)n * 4 + 3];
    const float b2 = w[4 * h];
    const int total = H * W;
    for (int idx = threadIdx.x; idx < total; idx += blockDim.x) {
        const int yy = idx / W;
        const int xx = idx - yy * W;
        const float rel_x = (((float)xx + 0.5f) / (float)W - cx) / bw;
        const float rel_y = (((float)yy + 0.5f) / (float)H - cy) / bh;
        float acc = b2;
        for (int k = 0; k < h; k++) {
            float pre = fmaf(rel_x, w[k], fmaf(rel_y, w[h + k], w[2 * h + k]));
            acc = fmaf(fmaxf(pre, 0.0f), w[3 * h + k], acc);
        }
        out[(size_t)n * total + idx] = acc;
    }
}

extern "C" void kernel_launch(void* const* d_in, const int* in_sizes, int n_in,
                              void* d_out, int out_size) {
    const float* pos = (const float*)d_in[0];
    const float* q   = (const float*)d_in[1];
    const float* Wg  = (const float*)d_in[2];
    const float* bg  = (const float*)d_in[3];
    float* out = (float*)d_out;

    const int N    = in_sizes[0] / 4;          // rows of pos
    const int dim  = in_sizes[1] / N;          // query dim
    const int cols = in_sizes[3];              // 4*h + 1
    const int HW   = out_size / N;
    const int H    = (int)(sqrt((double)HW) + 0.5);
    const int h    = (cols - 1) / 4;

    float* w_scratch;
    cudaGetSymbolAddress((void**)&w_scratch, g_weights);

    if (H == 64 && h == 16 && cols == 65 && dim == 256 && (N % 16) == 0) {
        const int smem_bytes = GTOT * sizeof(float);  // ~122 KB
        cudaFuncSetAttribute(posmlp_gemm_ksplit_kernel,
                             cudaFuncAttributeMaxDynamicSharedMemorySize, smem_bytes);
        posmlp_gemm_ksplit_kernel<<<N / 16, 256, smem_bytes>>>(q, Wg, bg, w_scratch);
        posmlp_bp64_kernel<<<N, 128>>>(pos, w_scratch, out);
    } else {
        posmlp_gemm_kernel<<<N, 256, dim * sizeof(float)>>>(q, Wg, bg, w_scratch, dim, cols);
        posmlp_generic_kernel<<<N, 256>>>(pos, w_scratch, out, H, H, h, cols);
    }
}

// round 8
// speedup vs baseline: 1.1391x; 1.1391x over previous
#include <cuda_runtime.h>
#include <math.h>

// Scratch for per-query MLP weights (N x cols). 4096*80 floats = 1.25 MB.
__device__ float g_weights[4096 * 80];

// ===========================================================================
// GEMM (fast path, dim=256, cols=65): weights = q @ Wg + bg.
// 150 CTAs x 256 threads, 16 n per CTA. K-split: warp w owns d in [32w,32w+32).
// Wg read straight from L2 (coalesced scalar LDGs — stride 65 is odd, so no
// vector loads; unroll-8 for MLP). q transposed in smem (stride 20; float4
// broadcasts). Partials tree-reduced through smem.
// ===========================================================================
#define GSQ   0                    // sqT: 256 x 20        = 5120 floats
#define GPR   5120                 // partials: 8*16 x 66  = 8448 floats
#define GP64  13568                // col64 partials: 8*16 = 128 floats
#define GTOT  13696

__global__ void __launch_bounds__(256)
posmlp_gemm_ksplit_kernel(const float* __restrict__ q,
                          const float* __restrict__ Wg,
                          const float* __restrict__ bg,
                          float* __restrict__ w_out) {
    extern __shared__ float sm[];
    const int n0   = blockIdx.x * 16;
    const int tid  = threadIdx.x;
    const int w    = tid >> 5;
    const int l    = tid & 31;

    // Stage q transposed: sqT[d*20 + nn] = q[(n0+nn)*256 + d].
    #pragma unroll
    for (int i = tid; i < 4096; i += 256) {
        const int nn = i >> 8;
        const int d  = i & 255;
        sm[GSQ + d * 20 + nn] = q[(size_t)n0 * 256 + i];
    }
    __syncthreads();

    const int d0 = w * 32;
    float2 acc[16];
    #pragma unroll
    for (int nn = 0; nn < 16; nn++) acc[nn] = make_float2(0.f, 0.f);
    float acc64[16];
    #pragma unroll
    for (int nn = 0; nn < 16; nn++) acc64[nn] = 0.f;

    #pragma unroll
    for (int db = 0; db < 32; db += 8) {
        float wpx[8], wpy[8], w64[8];
        #pragma unroll
        for (int j = 0; j < 8; j++) {
            const size_t base = (size_t)(d0 + db + j) * 65;
            wpx[j] = Wg[base + 2 * l];       // scalar LDGs: alignment-safe,
            wpy[j] = Wg[base + 2 * l + 1];   // warp covers 65 consecutive floats
            w64[j] = Wg[base + 64];
        }
        #pragma unroll
        for (int j = 0; j < 8; j++) {
            const int d = d0 + db + j;
            const float4 qa = *reinterpret_cast<const float4*>(&sm[GSQ + d * 20 + 0]);
            const float4 qb = *reinterpret_cast<const float4*>(&sm[GSQ + d * 20 + 4]);
            const float4 qc = *reinterpret_cast<const float4*>(&sm[GSQ + d * 20 + 8]);
            const float4 qd = *reinterpret_cast<const float4*>(&sm[GSQ + d * 20 + 12]);
            const float qv[16] = {qa.x, qa.y, qa.z, qa.w, qb.x, qb.y, qb.z, qb.w,
                                  qc.x, qc.y, qc.z, qc.w, qd.x, qd.y, qd.z, qd.w};
            #pragma unroll
            for (int nn = 0; nn < 16; nn++) {
                acc[nn].x = fmaf(qv[nn], wpx[j], acc[nn].x);
                acc[nn].y = fmaf(qv[nn], wpy[j], acc[nn].y);
            }
            if (l == 0) {
                #pragma unroll
                for (int nn = 0; nn < 16; nn++)
                    acc64[nn] = fmaf(qv[nn], w64[j], acc64[nn]);
            }
        }
    }

    #pragma unroll
    for (int nn = 0; nn < 16; nn++) {
        *reinterpret_cast<float2*>(&sm[GPR + (w * 16 + nn) * 66 + 2 * l]) = acc[nn];
    }
    if (l == 0) {
        #pragma unroll
        for (int nn = 0; nn < 16; nn++) sm[GP64 + w * 16 + nn] = acc64[nn];
    }
    __syncthreads();

    for (int o = tid; o < 1040; o += 256) {
        const int nn = o / 65;
        const int c  = o - nn * 65;
        float s = 0.f;
        if (c < 64) {
            #pragma unroll
            for (int w8 = 0; w8 < 8; w8++) s += sm[GPR + (w8 * 16 + nn) * 66 + c];
        } else {
            #pragma unroll
            for (int w8 = 0; w8 < 8; w8++) s += sm[GP64 + w8 * 16 + nn];
        }
        w_out[(size_t)(n0 + nn) * 65 + c] = s + bg[c];
    }
}

// ===========================================================================
// Main kernel (H=W=64, hidden=16): breakpoint/prefix sweep, v2.
// One CTA per n, 256 threads; thread t owns row y=t>>2, 16 px at (t&3)*16.
// Per-CTA unit tables in smem: u0[k]={w0,w1,b1,w2}, u1[k]={1/s, alpha=w2*s}
// (s = w0*sx identical across threads -> divide done ONCE, zero MUFU in the
// scatter loop). Breakpoints clamping to the window edge fold into (A0,B0)
// or are skipped entirely -> fewer serial smem RMWs. 48 warps/SM resident.
// ===========================================================================
__global__ void __launch_bounds__(256)
posmlp_bp16_kernel(const float* __restrict__ pos,
                   const float* __restrict__ wts,
                   float* __restrict__ out) {
    __shared__ float  sw[65];
    __shared__ float4 u0[16];
    __shared__ float2 u1[16];
    __shared__ float2 bins[17 * 256];

    const int n   = blockIdx.x;
    const int tid = threadIdx.x;

    if (tid < 65) sw[tid] = wts[(size_t)n * 65 + tid];
    const float4 p = *reinterpret_cast<const float4*>(&pos[(size_t)n * 4]);
    const float inv_bw = 1.0f / p.z;
    const float inv_bh = 1.0f / p.w;
    const float sx = inv_bw * (1.0f / 64.0f);
    const float tx = (0.5f * (1.0f / 64.0f) - p.x) * inv_bw;
    __syncthreads();

    if (tid < 16) {
        const int k = tid;
        const float w0 = sw[k];
        u0[k] = make_float4(w0, sw[16 + k], sw[32 + k], sw[48 + k]);
        const float s = w0 * sx;
        const float inv = (s != 0.f) ? __fdividef(1.0f, s) : 0.f;
        u1[k] = make_float2(inv, sw[48 + k] * s);
    }
    #pragma unroll
    for (int b = 0; b < 17; b++) bins[b * 256 + tid] = make_float2(0.f, 0.f);
    __syncthreads();

    const int y  = tid >> 2;
    const int qd = tid & 3;

    const float rel_y = (((float)y + 0.5f) * (1.0f / 64.0f) - p.y) * inv_bh;
    const float txh   = fmaf(16.0f * (float)qd, sx, tx);   // local-x origin

    float A0 = 0.f;
    float B0 = sw[64];

    #pragma unroll
    for (int k = 0; k < 16; k++) {
        const float4 a  = u0[k];             // w0, w1, b1, w2
        const float2 uu = u1[k];             // inv_s, alpha
        const float ay   = fmaf(rel_y, a.y, a.z);
        const float c    = fmaf(a.x, txh, ay);
        const float beta = a.w * c;
        const float alpha = uu.y;
        if (a.x > 0.f) {                     // s > 0: active for xl >= bi
            const float t = -c * uu.x;
            const int bi = (int)fminf(fmaxf(ceilf(t), 0.f), 16.f);
            if (bi == 0) { A0 += alpha; B0 += beta; }
            else if (bi < 16) {
                float2 v = bins[bi * 256 + tid];
                v.x += alpha; v.y += beta;
                bins[bi * 256 + tid] = v;
            }                                // bi == 16: never active, skip
        } else if (a.x < 0.f) {              // s < 0: active for xl < bi
            const float t = -c * uu.x;
            const int bi = (int)fminf(fmaxf(ceilf(t), 0.f), 16.f);
            if (bi == 16) { A0 += alpha; B0 += beta; }
            else if (bi > 0) {
                A0 += alpha; B0 += beta;
                float2 v = bins[bi * 256 + tid];
                v.x -= alpha; v.y -= beta;
                bins[bi * 256 + tid] = v;
            }                                // bi == 0: never active, skip
        } else {                             // s == 0: constant unit
            if (c > 0.f) B0 += beta;
        }
    }

    // Prefix sweep over 16 local pixels; float4 coalesced stores.
    float A = A0, B = B0;
    float xf = 0.f;
    float* orow = out + (((size_t)n * 64 + y) * 64 + qd * 16);

    #pragma unroll
    for (int xi = 0; xi < 16; xi += 4) {
        float4 res;
        float* rp = &res.x;
        #pragma unroll
        for (int j = 0; j < 4; j++) {
            const float2 d = bins[(xi + j) * 256 + tid];
            A += d.x;
            B += d.y;
            rp[j] = fmaf(A, xf, B);
            xf += 1.0f;
        }
        *reinterpret_cast<float4*>(orow + xi) = res;
    }
}

// ===========================================================================
// Fallback path (other shapes).
// ===========================================================================
__global__ void posmlp_gemm_kernel(const float* __restrict__ q,
                                   const float* __restrict__ Wg,
                                   const float* __restrict__ bg,
                                   float* __restrict__ w_out,
                                   int dim, int cols) {
    extern __shared__ float sqf[];
    const int n = blockIdx.x;
    const float* qr = q + (size_t)n * dim;
    for (int d = threadIdx.x; d < dim; d += blockDim.x) sqf[d] = qr[d];
    __syncthreads();
    for (int j = threadIdx.x; j < cols; j += blockDim.x) {
        float acc = bg[j];
        #pragma unroll 8
        for (int d = 0; d < dim; d++) {
            acc = fmaf(sqf[d], Wg[(size_t)d * cols + j], acc);
        }
        w_out[(size_t)n * cols + j] = acc;
    }
}

__global__ void posmlp_generic_kernel(const float* __restrict__ pos,
                                      const float* __restrict__ wts,
                                      float* __restrict__ out,
                                      int H, int W, int h, int cols) {
    const int n = blockIdx.x;
    const float* w = wts + (size_t)n * cols;
    const float cx = pos[(size_t)n * 4 + 0];
    const float cy = pos[(size_t)n * 4 + 1];
    const float bw = pos[(size_t)n * 4 + 2];
    const float bh = pos[(size_t)n * 4 + 3];
    const float b2 = w[4 * h];
    const int total = H * W;
    for (int idx = threadIdx.x; idx < total; idx += blockDim.x) {
        const int yy = idx / W;
        const int xx = idx - yy * W;
        const float rel_x = (((float)xx + 0.5f) / (float)W - cx) / bw;
        const float rel_y = (((float)yy + 0.5f) / (float)H - cy) / bh;
        float acc = b2;
        for (int k = 0; k < h; k++) {
            float pre = fmaf(rel_x, w[k], fmaf(rel_y, w[h + k], w[2 * h + k]));
            acc = fmaf(fmaxf(pre, 0.0f), w[3 * h + k], acc);
        }
        out[(size_t)n * total + idx] = acc;
    }
}

extern "C" void kernel_launch(void* const* d_in, const int* in_sizes, int n_in,
                              void* d_out, int out_size) {
    const float* pos = (const float*)d_in[0];
    const float* q   = (const float*)d_in[1];
    const float* Wg  = (const float*)d_in[2];
    const float* bg  = (const float*)d_in[3];
    float* out = (float*)d_out;

    const int N    = in_sizes[0] / 4;          // rows of pos
    const int dim  = in_sizes[1] / N;          // query dim
    const int cols = in_sizes[3];              // 4*h + 1
    const int HW   = out_size / N;
    const int H    = (int)(sqrt((double)HW) + 0.5);
    const int h    = (cols - 1) / 4;

    float* w_scratch;
    cudaGetSymbolAddress((void**)&w_scratch, g_weights);

    if (H == 64 && h == 16 && cols == 65 && dim == 256 && (N % 16) == 0) {
        const int smem_bytes = GTOT * sizeof(float);  // ~55 KB
        cudaFuncSetAttribute(posmlp_gemm_ksplit_kernel,
                             cudaFuncAttributeMaxDynamicSharedMemorySize, smem_bytes);
        posmlp_gemm_ksplit_kernel<<<N / 16, 256, smem_bytes>>>(q, Wg, bg, w_scratch);
        posmlp_bp16_kernel<<<N, 256>>>(pos, w_scratch, out);
    } else {
        posmlp_gemm_kernel<<<N, 256, dim * sizeof(float)>>>(q, Wg, bg, w_scratch, dim, cols);
        posmlp_generic_kernel<<<N, 256>>>(pos, w_scratch, out, H, H, h, cols);
    }
}